// round 2
// baseline (speedup 1.0000x reference)
#include <cuda_runtime.h>
#include <cuda_bf16.h>

// Problem constants (fixed by reference setup_inputs)
#define N_ROWS (1 << 18)   // 262144
#define DIM    512
#define NB     (1 << 18)   // histogram bins (top-18 bits of ordered key)
#define SHIFT  14          // 32 - 18
#define REG_C  0.1
#define EPS_F  2.2204460492503131e-16f

// Scratch (no allocations allowed)
__device__ float    g_out[N_ROWS];
__device__ float    g_B[N_ROWS];      // bucketed values
__device__ int      g_H[NB];          // bin histogram
__device__ int      g_ctr[NB];        // scatter counters
__device__ int      g_P[NB];          // per-chunk exclusive prefix
__device__ int      g_T[256];         // chunk totals
__device__ int      g_Tp[256];        // exclusive prefix of chunk totals
__device__ unsigned g_minkey;
__device__ double   g_acc[3];         // [0]=sum_v  [1]=term1  [2]=2*term2

// Order-preserving float -> uint key
__device__ __forceinline__ unsigned f2key(float v) {
    unsigned u = __float_as_uint(v);
    return (u & 0x80000000u) ? ~u : (u | 0x80000000u);
}
__device__ __forceinline__ float key2f(unsigned k) {
    return __uint_as_float((k & 0x80000000u) ? (k & 0x7FFFFFFFu) : ~k);
}

// ---------------------------------------------------------------------------
// 0) Zero scratch
// ---------------------------------------------------------------------------
__global__ void zero_kernel() {
    int i = blockIdx.x * blockDim.x + threadIdx.x;
    if (i < NB) { g_H[i] = 0; g_ctr[i] = 0; }
    if (i == 0) {
        g_minkey = 0xFFFFFFFFu;
        g_acc[0] = 0.0; g_acc[1] = 0.0; g_acc[2] = 0.0;
    }
}

// ---------------------------------------------------------------------------
// 1) Matvec (HBM-bound) fused with histogram build
// ---------------------------------------------------------------------------
__global__ void matvec_kernel(const float* __restrict__ x,
                              const float* __restrict__ w,
                              const float* __restrict__ b) {
    int warp = (blockIdx.x * blockDim.x + threadIdx.x) >> 5;
    int lane = threadIdx.x & 31;

    const float4* xr = reinterpret_cast<const float4*>(x + (size_t)warp * DIM);
    const float4* w4 = reinterpret_cast<const float4*>(w);

    float acc = 0.f;
#pragma unroll
    for (int it = 0; it < 4; it++) {
        float4 xv = xr[lane + it * 32];
        float4 wv = __ldg(&w4[lane + it * 32]);
        acc += xv.x * wv.x + xv.y * wv.y + xv.z * wv.z + xv.w * wv.w;
    }
#pragma unroll
    for (int o = 16; o > 0; o >>= 1)
        acc += __shfl_xor_sync(0xffffffffu, acc, o);

    if (lane == 0) {
        float v = acc + b[0];
        g_out[warp] = v;
        atomicAdd(&g_H[f2key(v) >> SHIFT], 1);
    }
}

// ---------------------------------------------------------------------------
// 2) Two-level exclusive scan of the histogram
// ---------------------------------------------------------------------------
__global__ __launch_bounds__(1024) void scan1_kernel() {
    __shared__ int sh[1024];
    int t = threadIdx.x;
    int g = blockIdx.x * 1024 + t;
    int v = g_H[g];
    sh[t] = v;
    __syncthreads();
#pragma unroll
    for (int o = 1; o < 1024; o <<= 1) {
        int add = (t >= o) ? sh[t - o] : 0;
        __syncthreads();
        sh[t] += add;
        __syncthreads();
    }
    g_P[g] = sh[t] - v;                 // exclusive within chunk
    if (t == 1023) g_T[blockIdx.x] = sh[t];
}

__global__ void scan2_kernel() {
    __shared__ int sh[256];
    int t = threadIdx.x;
    int v = g_T[t];
    sh[t] = v;
    __syncthreads();
#pragma unroll
    for (int o = 1; o < 256; o <<= 1) {
        int add = (t >= o) ? sh[t - o] : 0;
        __syncthreads();
        sh[t] += add;
        __syncthreads();
    }
    g_Tp[t] = sh[t] - v;
}

// ---------------------------------------------------------------------------
// 3) Counting scatter + term1 + sum + min  (all L2-resident)
// ---------------------------------------------------------------------------
__global__ __launch_bounds__(1024) void scatter_kernel() {
    __shared__ double sh_s[32], sh_t[32];
    __shared__ unsigned sh_m[32];
    int i = blockIdx.x * blockDim.x + threadIdx.x;
    int lane = threadIdx.x & 31, wid = threadIdx.x >> 5;

    float v = g_out[i];
    unsigned k = f2key(v);
    int d = (int)(k >> SHIFT);
    int base = g_P[d] + g_Tp[d >> 10];
    int pos = base + atomicAdd(&g_ctr[d], 1);
    g_B[pos] = v;

    double sv = (double)v;
    double t1 = (2.0 * (double)base + (double)g_H[d] - (double)N_ROWS) * sv;

#pragma unroll
    for (int o = 16; o > 0; o >>= 1) {
        sv += __shfl_down_sync(0xffffffffu, sv, o);
        t1 += __shfl_down_sync(0xffffffffu, t1, o);
        k = min(k, __shfl_down_sync(0xffffffffu, k, o));
    }
    if (lane == 0) { sh_s[wid] = sv; sh_t[wid] = t1; sh_m[wid] = k; }
    __syncthreads();
    if (wid == 0) {
        sv = sh_s[lane]; t1 = sh_t[lane]; k = sh_m[lane];
#pragma unroll
        for (int o = 16; o > 0; o >>= 1) {
            sv += __shfl_down_sync(0xffffffffu, sv, o);
            t1 += __shfl_down_sync(0xffffffffu, t1, o);
            k = min(k, __shfl_down_sync(0xffffffffu, k, o));
        }
        if (lane == 0) {
            atomicAdd(&g_acc[0], sv);
            atomicAdd(&g_acc[1], t1);
            atomicMin(&g_minkey, k);
        }
    }
}

// ---------------------------------------------------------------------------
// 4) In-bin pairwise |v_i - v_j| (each pair counted twice -> halve at the end)
// ---------------------------------------------------------------------------
__global__ __launch_bounds__(1024) void inbin_kernel() {
    __shared__ double sh[32];
    int i = blockIdx.x * blockDim.x + threadIdx.x;
    int lane = threadIdx.x & 31, wid = threadIdx.x >> 5;

    float v = g_out[i];
    unsigned k = f2key(v);
    int d = (int)(k >> SHIFT);
    int base = g_P[d] + g_Tp[d >> 10];
    int m = g_H[d];

    double s = 0.0;
    for (int j = 0; j < m; j++)
        s += (double)fabsf(v - g_B[base + j]);

#pragma unroll
    for (int o = 16; o > 0; o >>= 1)
        s += __shfl_down_sync(0xffffffffu, s, o);
    if (lane == 0) sh[wid] = s;
    __syncthreads();
    if (wid == 0) {
        s = sh[lane];
#pragma unroll
        for (int o = 16; o > 0; o >>= 1)
            s += __shfl_down_sync(0xffffffffu, s, o);
        if (lane == 0) atomicAdd(&g_acc[2], s);
    }
}

// ---------------------------------------------------------------------------
// 5) Finalize
// ---------------------------------------------------------------------------
__global__ void finalize_kernel(float* __restrict__ out) {
    double pair_sum = g_acc[1] + 0.5 * g_acc[2];
    double loss = -g_acc[0] + (REG_C / (double)N_ROWS) * pair_sum;
    out[0] = (float)loss;
    float minv = key2f(g_minkey);
    out[1] = ((minv + EPS_F) > 0.0f) ? 1.0f : 0.0f;
}

// ---------------------------------------------------------------------------
// Launch
// ---------------------------------------------------------------------------
extern "C" void kernel_launch(void* const* d_in, const int* in_sizes, int n_in,
                              void* d_out, int out_size) {
    const float* x = (const float*)d_in[0];
    const float* w = (const float*)d_in[1];
    const float* b = (const float*)d_in[2];
    float* out = (float*)d_out;

    zero_kernel<<<NB / 256, 256>>>();
    matvec_kernel<<<N_ROWS / 8, 256>>>(x, w, b);
    scan1_kernel<<<NB / 1024, 1024>>>();
    scan2_kernel<<<1, 256>>>();
    scatter_kernel<<<N_ROWS / 1024, 1024>>>();
    inbin_kernel<<<N_ROWS / 1024, 1024>>>();
    finalize_kernel<<<1, 1>>>(out);
}

// round 6
// speedup vs baseline: 1.9939x; 1.9939x over previous
#include <cuda_runtime.h>
#include <cuda_bf16.h>

// Problem constants (fixed by reference setup_inputs)
#define N_ROWS (1 << 18)   // 262144
#define DIM    512
#define NB     (1 << 18)   // histogram bins (top-18 bits of ordered key)
#define SHIFT  14          // 32 - 18
#define REG_C  0.1
#define EPS_F  2.2204460492503131e-16f

// Scratch (no allocations allowed)
__device__ float    g_out[N_ROWS];
__device__ float    g_B[N_ROWS];      // bucketed values (contiguous per bin)
__device__ int      g_H[NB];          // bin histogram
__device__ int      g_ctr[NB];        // scatter counters
__device__ int      g_P[NB];          // per-chunk exclusive prefix
__device__ int      g_T[256];         // chunk totals
__device__ int      g_Tp[256];        // exclusive prefix of chunk totals
__device__ unsigned g_minkey;
__device__ double   g_acc[3];         // [0]=sum_v  [1]=term1  [2]=2*term2

// Order-preserving float -> uint key
__device__ __forceinline__ unsigned f2key(float v) {
    unsigned u = __float_as_uint(v);
    return (u & 0x80000000u) ? ~u : (u | 0x80000000u);
}
__device__ __forceinline__ float key2f(unsigned k) {
    return __uint_as_float((k & 0x80000000u) ? (k & 0x7FFFFFFFu) : ~k);
}

// ---------------------------------------------------------------------------
// 0) Zero scratch
// ---------------------------------------------------------------------------
__global__ void zero_kernel() {
    int i = blockIdx.x * blockDim.x + threadIdx.x;
    // vectorized zero of H and ctr (int2 per thread each)
    reinterpret_cast<int2*>(g_H)[i]   = make_int2(0, 0);
    reinterpret_cast<int2*>(g_ctr)[i] = make_int2(0, 0);
    if (i == 0) {
        g_minkey = 0xFFFFFFFFu;
        g_acc[0] = 0.0; g_acc[1] = 0.0; g_acc[2] = 0.0;
    }
}

// ---------------------------------------------------------------------------
// 1) Matvec (HBM-bound) fused with histogram build
// ---------------------------------------------------------------------------
__global__ void matvec_kernel(const float* __restrict__ x,
                              const float* __restrict__ w,
                              const float* __restrict__ b) {
    int warp = (blockIdx.x * blockDim.x + threadIdx.x) >> 5;
    int lane = threadIdx.x & 31;

    const float4* xr = reinterpret_cast<const float4*>(x + (size_t)warp * DIM);
    const float4* w4 = reinterpret_cast<const float4*>(w);

    float acc = 0.f;
#pragma unroll
    for (int it = 0; it < 4; it++) {
        float4 xv = xr[lane + it * 32];
        float4 wv = __ldg(&w4[lane + it * 32]);
        acc += xv.x * wv.x + xv.y * wv.y + xv.z * wv.z + xv.w * wv.w;
    }
#pragma unroll
    for (int o = 16; o > 0; o >>= 1)
        acc += __shfl_xor_sync(0xffffffffu, acc, o);

    if (lane == 0) {
        float v = acc + b[0];
        g_out[warp] = v;
        atomicAdd(&g_H[f2key(v) >> SHIFT], 1);
    }
}

// ---------------------------------------------------------------------------
// 2) Two-level exclusive scan of the histogram
// ---------------------------------------------------------------------------
__global__ __launch_bounds__(1024) void scan1_kernel() {
    __shared__ int warp_tot[32];
    int t = threadIdx.x;
    int lane = t & 31, wid = t >> 5;
    int g = blockIdx.x * 1024 + t;
    int v = g_H[g];

    // warp inclusive scan
    int s = v;
#pragma unroll
    for (int o = 1; o < 32; o <<= 1) {
        int u = __shfl_up_sync(0xffffffffu, s, o);
        if (lane >= o) s += u;
    }
    if (lane == 31) warp_tot[wid] = s;
    __syncthreads();
    if (wid == 0) {
        int ws = warp_tot[lane];
#pragma unroll
        for (int o = 1; o < 32; o <<= 1) {
            int u = __shfl_up_sync(0xffffffffu, ws, o);
            if (lane >= o) ws += u;
        }
        warp_tot[lane] = ws;
    }
    __syncthreads();
    int pre = (wid > 0) ? warp_tot[wid - 1] : 0;
    g_P[g] = pre + s - v;               // exclusive within chunk
    if (t == 1023) g_T[blockIdx.x] = pre + s;
}

__global__ void scan2_kernel() {
    __shared__ int warp_tot[8];
    int t = threadIdx.x;                // 256 threads
    int lane = t & 31, wid = t >> 5;
    int v = g_T[t];
    int s = v;
#pragma unroll
    for (int o = 1; o < 32; o <<= 1) {
        int u = __shfl_up_sync(0xffffffffu, s, o);
        if (lane >= o) s += u;
    }
    if (lane == 31) warp_tot[wid] = s;
    __syncthreads();
    int pre = 0;
    for (int i = 0; i < wid; i++) pre += warp_tot[i];
    g_Tp[t] = pre + s - v;
}

// ---------------------------------------------------------------------------
// 3) Counting scatter + term1 + sum + min  (all L2-resident)
// ---------------------------------------------------------------------------
__global__ __launch_bounds__(1024) void scatter_kernel() {
    __shared__ double sh_s[32], sh_t[32];
    __shared__ unsigned sh_m[32];
    int i = blockIdx.x * blockDim.x + threadIdx.x;
    int lane = threadIdx.x & 31, wid = threadIdx.x >> 5;

    float v = g_out[i];
    unsigned k = f2key(v);
    int d = (int)(k >> SHIFT);
    int base = g_P[d] + g_Tp[d >> 10];
    int pos = base + atomicAdd(&g_ctr[d], 1);
    g_B[pos] = v;

    double sv = (double)v;
    double t1 = (2.0 * (double)base + (double)g_H[d] - (double)N_ROWS) * sv;

#pragma unroll
    for (int o = 16; o > 0; o >>= 1) {
        sv += __shfl_down_sync(0xffffffffu, sv, o);
        t1 += __shfl_down_sync(0xffffffffu, t1, o);
        k = min(k, __shfl_down_sync(0xffffffffu, k, o));
    }
    if (lane == 0) { sh_s[wid] = sv; sh_t[wid] = t1; sh_m[wid] = k; }
    __syncthreads();
    if (wid == 0) {
        sv = sh_s[lane]; t1 = sh_t[lane]; k = sh_m[lane];
#pragma unroll
        for (int o = 16; o > 0; o >>= 1) {
            sv += __shfl_down_sync(0xffffffffu, sv, o);
            t1 += __shfl_down_sync(0xffffffffu, t1, o);
            k = min(k, __shfl_down_sync(0xffffffffu, k, o));
        }
        if (lane == 0) {
            atomicAdd(&g_acc[0], sv);
            atomicAdd(&g_acc[1], t1);
            atomicMin(&g_minkey, k);
        }
    }
}

// ---------------------------------------------------------------------------
// 4) In-bin pairwise |v_i - v_j|  — ONE WARP PER BIN
//    Lane l holds element base + r*32 + l (coalesced); inner loop over j
//    reads g_B[base+j] at a uniform warp address (broadcast, 1 wavefront).
//    Accumulate fp32 (in-bin diffs <= bin width ~0.05 -> error negligible),
//    each unordered pair counted twice -> halved at finalize.
// ---------------------------------------------------------------------------
__global__ __launch_bounds__(256) void inbin_kernel() {
    int warp_g = (blockIdx.x * blockDim.x + threadIdx.x) >> 5;  // = bin id
    int lane = threadIdx.x & 31;

    int m = g_H[warp_g];          // uniform per warp -> broadcast
    if (m <= 1) return;           // empty / singleton bin: no pairs
    int base = g_P[warp_g] + g_Tp[warp_g >> 10];

    float s = 0.f;
    for (int r = 0; r < m; r += 32) {
        int idx = r + lane;
        float v = (idx < m) ? g_B[base + idx] : 0.f;
        bool valid = (idx < m);
        for (int j = 0; j < m; j++) {
            float u = __ldg(&g_B[base + j]);    // uniform -> broadcast
            if (valid) s += fabsf(v - u);
        }
    }
    // warp reduce (fp32 -> double once)
#pragma unroll
    for (int o = 16; o > 0; o >>= 1)
        s += __shfl_down_sync(0xffffffffu, s, o);
    if (lane == 0 && s != 0.f)
        atomicAdd(&g_acc[2], (double)s);
}

// ---------------------------------------------------------------------------
// 5) Finalize
// ---------------------------------------------------------------------------
__global__ void finalize_kernel(float* __restrict__ out) {
    double pair_sum = g_acc[1] + 0.5 * g_acc[2];
    double loss = -g_acc[0] + (REG_C / (double)N_ROWS) * pair_sum;
    out[0] = (float)loss;
    float minv = key2f(g_minkey);
    out[1] = ((minv + EPS_F) > 0.0f) ? 1.0f : 0.0f;
}

// ---------------------------------------------------------------------------
// Launch
// ---------------------------------------------------------------------------
extern "C" void kernel_launch(void* const* d_in, const int* in_sizes, int n_in,
                              void* d_out, int out_size) {
    const float* x = (const float*)d_in[0];
    const float* w = (const float*)d_in[1];
    const float* b = (const float*)d_in[2];
    float* out = (float*)d_out;

    zero_kernel<<<NB / 512, 256>>>();               // int2 per thread
    matvec_kernel<<<N_ROWS / 8, 256>>>(x, w, b);
    scan1_kernel<<<NB / 1024, 1024>>>();
    scan2_kernel<<<1, 256>>>();
    scatter_kernel<<<N_ROWS / 1024, 1024>>>();
    inbin_kernel<<<NB / 8, 256>>>();                // 1 warp per bin
    finalize_kernel<<<1, 1>>>(out);
}